// round 7
// baseline (speedup 1.0000x reference)
#include <cuda_runtime.h>
#include <cstdint>

#define NT 512
#define NS 64

typedef unsigned long long u64;

// ---------------- packed weights (j-pair, k-pair interleaved) ---------------------------
// g_whp[g][k2][jp] = (w_hh[g*256+2jp][2k2], w_hh[g*256+2jp+1][2k2],
//                     w_hh[g*256+2jp][2k2+1], w_hh[g*256+2jp+1][2k2+1])
__device__ float4 g_whp[3 * 128 * 128];
__device__ float4 g_wip[3 * 32 * 128];
__device__ float4 g_wbp[128 * 128];

// ---------------- f32x2 helpers ---------------------------------------------------------
__device__ __forceinline__ u64 pk2(float a, float b) {
    u64 r;
    asm("mov.b64 %0,{%1,%2};" : "=l"(r)
        : "r"(__float_as_uint(a)), "r"(__float_as_uint(b)));
    return r;
}
__device__ __forceinline__ float2 upk2(u64 v) {
    unsigned lo, hi;
    asm("mov.b64 {%0,%1},%2;" : "=r"(lo), "=r"(hi) : "l"(v));
    return make_float2(__uint_as_float(lo), __uint_as_float(hi));
}
__device__ __forceinline__ void ffma2(u64& d, u64 a, u64 b) {
    asm("fma.rn.f32x2 %0,%1,%2,%3;" : "=l"(d) : "l"(a), "l"(b), "l"(d));
}
__device__ __forceinline__ float sigmoidf_(float x) { return 1.f / (1.f + __expf(-x)); }
__device__ __forceinline__ float tanhf_(float x) { return 1.f - 2.f / (__expf(2.f * x) + 1.f); }

// one k-pair contribution into one packed accumulator
#define GSTEP(acc, wv, hv)      \
    do {                        \
        ffma2(acc, (wv).x, (hv).x); \
        ffma2(acc, (wv).y, (hv).y); \
    } while (0)

// ---------------- prep: pack weights ----------------------------------------------------
__global__ void __launch_bounds__(256) prep_kernel(const float* __restrict__ w_ih,
                                                   const float* __restrict__ w_hh,
                                                   const float* __restrict__ w_base) {
    int idx = blockIdx.x * 256 + threadIdx.x;
    const int T1 = 3 * 128 * 128;   // whp
    const int T2 = 3 * 32 * 128;    // wip
    const int T3 = 128 * 128;       // wbp
    if (idx < T1) {
        int g = idx / (128 * 128);
        int rem = idx % (128 * 128);
        int k2 = rem >> 7, jp = rem & 127;
        const float* base = w_hh + (size_t)(g * 256 + 2 * jp) * 256;
        g_whp[idx] = make_float4(base[2 * k2], base[256 + 2 * k2],
                                 base[2 * k2 + 1], base[256 + 2 * k2 + 1]);
        return;
    }
    idx -= T1;
    if (idx < T2) {
        int g = idx / (32 * 128);
        int rem = idx % (32 * 128);
        int k2 = rem >> 7, jp = rem & 127;
        const float* base = w_ih + (size_t)(g * 256 + 2 * jp) * 64;
        g_wip[idx] = make_float4(base[2 * k2], base[64 + 2 * k2],
                                 base[2 * k2 + 1], base[64 + 2 * k2 + 1]);
        return;
    }
    idx -= T2;
    if (idx < T3) {
        int k2 = idx >> 7, jp = idx & 127;
        const float* base = w_base + (size_t)(2 * jp) * 256;
        g_wbp[idx] = make_float4(base[2 * k2], base[256 + 2 * k2],
                                 base[2 * k2 + 1], base[256 + 2 * k2 + 1]);
    }
}

// ---------------- main: 128 CTAs x 128 threads; 8 rows/CTA; thread owns j-pair ----------
__global__ void __launch_bounds__(128, 1) actor_kernel(
    const float* __restrict__ x, const float* __restrict__ b_ih,
    const float* __restrict__ b_hh, const float* __restrict__ b_base,
    const float* __restrict__ w_dir, const float* __restrict__ b_dir,
    const float* __restrict__ w_mag, const float* __restrict__ b_mag,
    float* __restrict__ out) {
    // hdup[b][k2] = (dup(h[b][2k2]), dup(h[b][2k2+1])) — written coalesced, read broadcast
    __shared__ ulonglong2 hdup[8][128];
    __shared__ ulonglong2 xdup[2][8][32];
    __shared__ float hbs[8][256];

    const int tid = threadIdx.x;      // j-pair index: j0 = 2*tid, j1 = 2*tid+1
    const int bbase = blockIdx.x * 8;

    // biases for this thread's two gate dims (gate order r,z,n)
    const float br0 = b_ih[2 * tid] + b_hh[2 * tid];
    const float br1 = b_ih[2 * tid + 1] + b_hh[2 * tid + 1];
    const float bz0 = b_ih[256 + 2 * tid] + b_hh[256 + 2 * tid];
    const float bz1 = b_ih[256 + 2 * tid + 1] + b_hh[256 + 2 * tid + 1];
    const float bi0 = b_ih[512 + 2 * tid], bi1 = b_ih[512 + 2 * tid + 1];
    const float bh0 = b_hh[512 + 2 * tid], bh1 = b_hh[512 + 2 * tid + 1];

    float hreg[16];                   // hreg[2b+s] = h[b][2*tid+s]
#pragma unroll
    for (int i = 0; i < 16; i++) hreg[i] = 0.f;
#pragma unroll
    for (int b = 0; b < 8; b++) hdup[b][tid] = make_ulonglong2(0ULL, 0ULL);

    // x prefetch: thread loads one float4 of x per step
    const int xrow = tid >> 4, xc = tid & 15;
    const float* xptr = x + (size_t)(bbase + xrow) * NT * NS + xc * 4;
    float4 xr = *(const float4*)xptr;

    const float4* __restrict__ whR = g_whp;
    const float4* __restrict__ whZ = g_whp + 128 * 128;
    const float4* __restrict__ whN = g_whp + 2 * 128 * 128;
    const float4* __restrict__ wiR = g_wip;
    const float4* __restrict__ wiZ = g_wip + 32 * 128;
    const float4* __restrict__ wiN = g_wip + 2 * 32 * 128;

    for (int t = 0; t < NT; ++t) {
        const int buf = t & 1;
        // stage x_t (already in regs) into dup'd SMEM
        xdup[buf][xrow][2 * xc] = make_ulonglong2(pk2(xr.x, xr.x), pk2(xr.y, xr.y));
        xdup[buf][xrow][2 * xc + 1] = make_ulonglong2(pk2(xr.z, xr.z), pk2(xr.w, xr.w));
        if (t + 1 < NT) xr = *(const float4*)(xptr + (size_t)(t + 1) * NS);
        __syncthreads();  // x_t staged; hdup of t-1 visible

        u64 aR[8], aZ[8], aNi[8], aNh[8];
#pragma unroll
        for (int b = 0; b < 8; b++) { aR[b] = aZ[b] = aNi[b] = aNh[b] = 0ULL; }

        // input contribution (64 k's = 32 k-pairs)
#pragma unroll 4
        for (int k2 = 0; k2 < 32; ++k2) {
            ulonglong2 wr = *(const ulonglong2*)(wiR + k2 * 128 + tid);
            ulonglong2 wz = *(const ulonglong2*)(wiZ + k2 * 128 + tid);
            ulonglong2 wn = *(const ulonglong2*)(wiN + k2 * 128 + tid);
#pragma unroll
            for (int b = 0; b < 8; b++) {
                ulonglong2 hv = xdup[buf][b][k2];
                GSTEP(aR[b], wr, hv);
                GSTEP(aZ[b], wz, hv);
                GSTEP(aNi[b], wn, hv);
            }
        }
        // recurrent contribution (256 k's = 128 k-pairs)
#pragma unroll 4
        for (int k2 = 0; k2 < 128; ++k2) {
            ulonglong2 wr = *(const ulonglong2*)(whR + k2 * 128 + tid);
            ulonglong2 wz = *(const ulonglong2*)(whZ + k2 * 128 + tid);
            ulonglong2 wn = *(const ulonglong2*)(whN + k2 * 128 + tid);
#pragma unroll
            for (int b = 0; b < 8; b++) {
                ulonglong2 hv = hdup[b][k2];
                GSTEP(aR[b], wr, hv);
                GSTEP(aZ[b], wz, hv);
                GSTEP(aNh[b], wn, hv);
            }
        }

        // gates
#pragma unroll
        for (int b = 0; b < 8; b++) {
            float2 rv = upk2(aR[b]), zv = upk2(aZ[b]);
            float2 iv = upk2(aNi[b]), hv = upk2(aNh[b]);
            float r0 = sigmoidf_(rv.x + br0);
            float z0 = sigmoidf_(zv.x + bz0);
            float n0 = tanhf_(iv.x + bi0 + r0 * (hv.x + bh0));
            hreg[2 * b] = (1.f - z0) * n0 + z0 * hreg[2 * b];
            float r1 = sigmoidf_(rv.y + br1);
            float z1 = sigmoidf_(zv.y + bz1);
            float n1 = tanhf_(iv.y + bi1 + r1 * (hv.y + bh1));
            hreg[2 * b + 1] = (1.f - z1) * n1 + z1 * hreg[2 * b + 1];
        }

        __syncthreads();  // all reads of hdup done
#pragma unroll
        for (int b = 0; b < 8; b++) {
            hdup[b][tid] = make_ulonglong2(pk2(hreg[2 * b], hreg[2 * b]),
                                           pk2(hreg[2 * b + 1], hreg[2 * b + 1]));
        }
    }
    __syncthreads();  // final h visible

    // base layer: hb[b][i] = relu(h[b] . w_base[i] + b_base[i]); thread owns i-pair
    {
        u64 aB[8];
#pragma unroll
        for (int b = 0; b < 8; b++) aB[b] = 0ULL;
#pragma unroll 4
        for (int k2 = 0; k2 < 128; ++k2) {
            ulonglong2 wb = *(const ulonglong2*)(g_wbp + k2 * 128 + tid);
#pragma unroll
            for (int b = 0; b < 8; b++) {
                ulonglong2 hv = hdup[b][k2];
                GSTEP(aB[b], wb, hv);
            }
        }
        float bb0 = b_base[2 * tid], bb1 = b_base[2 * tid + 1];
#pragma unroll
        for (int b = 0; b < 8; b++) {
            float2 v = upk2(aB[b]);
            hbs[b][2 * tid] = fmaxf(v.x + bb0, 0.f);
            hbs[b][2 * tid + 1] = fmaxf(v.y + bb1, 0.f);
        }
    }
    __syncthreads();

    // factorized heads: 64 outputs per CTA
    if (tid < 64) {
        int b = tid >> 3, a = tid & 7;
        float aD = b_dir[a], aM = b_mag[a];
        const float* __restrict__ wd = w_dir + a * 256;
        const float* __restrict__ wm = w_mag + a * 256;
#pragma unroll 4
        for (int k = 0; k < 256; ++k) {
            float hv = hbs[b][k];
            aD = fmaf(wd[k], hv, aD);
            aM = fmaf(wm[k], hv, aM);
        }
        out[(size_t)(bbase + b) * 8 + a] = tanhf_(aD) * sigmoidf_(aM);
    }
}

// ---------------- launch ----------------------------------------------------------------
extern "C" void kernel_launch(void* const* d_in, const int* in_sizes, int n_in,
                              void* d_out, int out_size) {
    const float* x      = (const float*)d_in[0];
    const float* w_ih   = (const float*)d_in[1];
    const float* w_hh   = (const float*)d_in[2];
    const float* b_ih   = (const float*)d_in[3];
    const float* b_hh   = (const float*)d_in[4];
    const float* w_base = (const float*)d_in[5];
    const float* b_base = (const float*)d_in[6];
    const float* w_dir  = (const float*)d_in[7];
    const float* b_dir  = (const float*)d_in[8];
    const float* w_mag  = (const float*)d_in[9];
    const float* b_mag  = (const float*)d_in[10];

    // (3*128*128 + 3*32*128 + 128*128) = 77824 elements -> 304 blocks of 256
    prep_kernel<<<304, 256>>>(w_ih, w_hh, w_base);
    actor_kernel<<<128, 128>>>(x, b_ih, b_hh, b_base, w_dir, b_dir, w_mag, b_mag,
                               (float*)d_out);
}

// round 8
// speedup vs baseline: 1.2469x; 1.2469x over previous
#include <cuda_runtime.h>
#include <cstdint>

#define NT 512
#define NS 64

typedef unsigned long long u64;

// ---------------- packed weights: [gate][k-pair][j] = (w[g*256+j][2k2], w[g*256+j][2k2+1])
__device__ float2 g_whP[3 * 128 * 256];
__device__ float2 g_wiP[3 * 32 * 256];
__device__ float2 g_wbP[128 * 256];

// ---------------- f32x2 helpers ---------------------------------------------------------
__device__ __forceinline__ u64 pk2(float a, float b) {
    u64 r;
    asm("mov.b64 %0,{%1,%2};" : "=l"(r)
        : "r"(__float_as_uint(a)), "r"(__float_as_uint(b)));
    return r;
}
__device__ __forceinline__ float2 upk2(u64 v) {
    unsigned lo, hi;
    asm("mov.b64 {%0,%1},%2;" : "=r"(lo), "=r"(hi) : "l"(v));
    return make_float2(__uint_as_float(lo), __uint_as_float(hi));
}
__device__ __forceinline__ void ffma2(u64& d, u64 a, u64 b) {
    asm("fma.rn.f32x2 %0,%1,%2,%3;" : "=l"(d) : "l"(a), "l"(b), "l"(d));
}
__device__ __forceinline__ float hsum2(u64 v) {
    float2 f = upk2(v);
    return f.x + f.y;
}
__device__ __forceinline__ float sigmoidf_(float x) { return 1.f / (1.f + __expf(-x)); }
__device__ __forceinline__ float tanhf_(float x) { return 1.f - 2.f / (__expf(2.f * x) + 1.f); }

// ---------------- prep: transpose + k-pair pack weights (same as R5, verified) ----------
__global__ void __launch_bounds__(256) prep_kernel(const float* __restrict__ w_ih,
                                                   const float* __restrict__ w_hh,
                                                   const float* __restrict__ w_base) {
    int idx = blockIdx.x * 256 + threadIdx.x;
    if (idx < 3 * 128 * 256) {
        int g = idx / (128 * 256);
        int rem = idx % (128 * 256);
        int k2 = rem >> 8;
        int j = rem & 255;
        const float* row = w_hh + (size_t)(g * 256 + j) * 256;
        g_whP[idx] = make_float2(row[2 * k2], row[2 * k2 + 1]);
        return;
    }
    int i2 = idx - 3 * 128 * 256;
    if (i2 < 3 * 32 * 256) {
        int g = i2 / (32 * 256);
        int rem = i2 % (32 * 256);
        int k2 = rem >> 8;
        int j = rem & 255;
        const float* row = w_ih + (size_t)(g * 256 + j) * 64;
        g_wiP[i2] = make_float2(row[2 * k2], row[2 * k2 + 1]);
        return;
    }
    int i3 = i2 - 3 * 32 * 256;
    if (i3 < 128 * 256) {
        int k2 = i3 >> 8;
        int j = i3 & 255;
        const float* row = w_base + (size_t)j * 256;
        g_wbP[i3] = make_float2(row[2 * k2], row[2 * k2 + 1]);
    }
}

// ---------------- main: 128 CTAs x 512 threads; 8 rows/CTA; thread = (j, k-half) --------
// hs[k2][bp] floats: [h[2bp][2k2], h[2bp][2k2+1], h[2bp+1][2k2], h[2bp+1][2k2+1]]
__global__ void __launch_bounds__(512, 1) actor_kernel(
    const float* __restrict__ x, const float* __restrict__ b_ih,
    const float* __restrict__ b_hh, const float* __restrict__ b_base,
    const float* __restrict__ w_dir, const float* __restrict__ b_dir,
    const float* __restrict__ w_mag, const float* __restrict__ b_mag,
    float* __restrict__ out) {
    __shared__ ulonglong2 hs[128][4];     // 8 KB
    __shared__ ulonglong2 xs[2][32][4];   // 4 KB
    __shared__ float4 exch[8][256];       // 32 KB (also reused as hbs/base-exchange)

    const int tid = threadIdx.x;
    const int j = tid & 255;   // gate dim
    const int kh = tid >> 8;   // k-half: 0 -> k2 [0,64), 1 -> [64,128)
    const int bbase = blockIdx.x * 8;

    ((ulonglong2*)hs)[tid] = make_ulonglong2(0ULL, 0ULL);

    const float br = b_ih[j] + b_hh[j];
    const float bz = b_ih[256 + j] + b_hh[256 + j];
    const float bi = b_ih[512 + j];
    const float bh = b_hh[512 + j];

    float hreg[8];
#pragma unroll
    for (int i = 0; i < 8; i++) hreg[i] = 0.f;

    // x prefetch: threads 0..127 each own (row, 4-float chunk)
    const int xrow = tid >> 4, xc = tid & 15;
    const float* xptr = x + (size_t)(bbase + xrow) * NT * NS + xc * 4;
    float4 xr = make_float4(0.f, 0.f, 0.f, 0.f);
    if (tid < 128) xr = *(const float4*)xptr;

    const u64* pW = (const u64*)g_whP + (size_t)kh * 64 * 256 + j;
    const u64* pWi = (const u64*)g_wiP + (size_t)kh * 16 * 256 + j;
    const ulonglong2* hbase = &hs[kh * 64][0];

    for (int t = 0; t < NT; ++t) {
        const int buf = t & 1;
        if (tid < 128) {
            ((u64*)&xs[buf][2 * xc][xrow >> 1])[xrow & 1] = pk2(xr.x, xr.y);
            ((u64*)&xs[buf][2 * xc + 1][xrow >> 1])[xrow & 1] = pk2(xr.z, xr.w);
            if (t + 1 < NT) xr = *(const float4*)(xptr + (size_t)(t + 1) * NS);
        }
        __syncthreads();  // x_t staged; h(t-1) visible; exch free

        u64 aR[8], aZ[8], aNi[8], aNh[8];
#pragma unroll
        for (int b = 0; b < 8; b++) { aR[b] = aZ[b] = aNi[b] = aNh[b] = 0ULL; }

        // input part: 16 k-pairs for this k-half
        const ulonglong2* xbase = &xs[buf][kh * 16][0];
#pragma unroll 2
        for (int k2 = 0; k2 < 16; ++k2) {
            u64 wr = pWi[k2 * 256];
            u64 wz = pWi[k2 * 256 + 32 * 256];
            u64 wn = pWi[k2 * 256 + 64 * 256];
#pragma unroll
            for (int bp = 0; bp < 4; ++bp) {
                ulonglong2 hv = xbase[k2 * 4 + bp];
                ffma2(aR[2 * bp], wr, hv.x);
                ffma2(aR[2 * bp + 1], wr, hv.y);
                ffma2(aZ[2 * bp], wz, hv.x);
                ffma2(aZ[2 * bp + 1], wz, hv.y);
                ffma2(aNi[2 * bp], wn, hv.x);
                ffma2(aNi[2 * bp + 1], wn, hv.y);
            }
        }
        // recurrent part: 64 k-pairs for this k-half
#pragma unroll 2
        for (int k2 = 0; k2 < 64; ++k2) {
            u64 wr = pW[k2 * 256];
            u64 wz = pW[k2 * 256 + 128 * 256];
            u64 wn = pW[k2 * 256 + 256 * 256];
#pragma unroll
            for (int bp = 0; bp < 4; ++bp) {
                ulonglong2 hv = hbase[k2 * 4 + bp];
                ffma2(aR[2 * bp], wr, hv.x);
                ffma2(aR[2 * bp + 1], wr, hv.y);
                ffma2(aZ[2 * bp], wz, hv.x);
                ffma2(aZ[2 * bp + 1], wz, hv.y);
                ffma2(aNh[2 * bp], wn, hv.x);
                ffma2(aNh[2 * bp + 1], wn, hv.y);
            }
        }

        // kh=1 publishes horizontally-reduced partials
        if (kh) {
#pragma unroll
            for (int b = 0; b < 8; ++b)
                exch[b][j] = make_float4(hsum2(aR[b]), hsum2(aZ[b]),
                                         hsum2(aNi[b]), hsum2(aNh[b]));
        }
        __syncthreads();  // exch ready; all hs reads done

        // kh=0 combines, does gate math, writes new h
        if (!kh) {
            const int k2w = j >> 1, par = j & 1;
#pragma unroll
            for (int b = 0; b < 8; ++b) {
                float4 p = exch[b][j];
                float r = sigmoidf_(hsum2(aR[b]) + p.x + br);
                float z = sigmoidf_(hsum2(aZ[b]) + p.y + bz);
                float n = tanhf_(hsum2(aNi[b]) + p.z + bi +
                                 r * (hsum2(aNh[b]) + p.w + bh));
                hreg[b] = (1.f - z) * n + z * hreg[b];
                ((float*)&hs[k2w][b >> 1])[(b & 1) * 2 + par] = hreg[b];
            }
        }
    }
    __syncthreads();  // final h visible

    // base layer (k-split too): hb[b][j] = relu(h[b] . w_base[j] + b_base[j])
    {
        u64 aB[8];
#pragma unroll
        for (int b = 0; b < 8; b++) aB[b] = 0ULL;
        const u64* pWb = (const u64*)g_wbP + (size_t)kh * 64 * 256 + j;
#pragma unroll 2
        for (int k2 = 0; k2 < 64; ++k2) {
            u64 wb = pWb[k2 * 256];
#pragma unroll
            for (int bp = 0; bp < 4; ++bp) {
                ulonglong2 hv = hbase[k2 * 4 + bp];
                ffma2(aB[2 * bp], wb, hv.x);
                ffma2(aB[2 * bp + 1], wb, hv.y);
            }
        }
        float* exf = (float*)exch;
        if (kh) {
#pragma unroll
            for (int b = 0; b < 8; ++b) exf[b * 256 + j] = hsum2(aB[b]);
        }
        __syncthreads();
        if (!kh) {
            float bb = b_base[j];
#pragma unroll
            for (int b = 0; b < 8; ++b)
                exf[b * 256 + j] = fmaxf(hsum2(aB[b]) + exf[b * 256 + j] + bb, 0.f);
        }
        __syncthreads();
    }

    // factorized heads: 64 outputs per CTA
    if (tid < 64) {
        const float* hb = (const float*)exch;
        int b = tid >> 3, a = tid & 7;
        float aD = b_dir[a], aM = b_mag[a];
        const float* __restrict__ wd = w_dir + a * 256;
        const float* __restrict__ wm = w_mag + a * 256;
#pragma unroll 4
        for (int k = 0; k < 256; ++k) {
            float hv = hb[b * 256 + k];
            aD = fmaf(wd[k], hv, aD);
            aM = fmaf(wm[k], hv, aM);
        }
        out[(size_t)(bbase + b) * 8 + a] = tanhf_(aD) * sigmoidf_(aM);
    }
}

// ---------------- launch ----------------------------------------------------------------
extern "C" void kernel_launch(void* const* d_in, const int* in_sizes, int n_in,
                              void* d_out, int out_size) {
    const float* x      = (const float*)d_in[0];
    const float* w_ih   = (const float*)d_in[1];
    const float* w_hh   = (const float*)d_in[2];
    const float* b_ih   = (const float*)d_in[3];
    const float* b_hh   = (const float*)d_in[4];
    const float* w_base = (const float*)d_in[5];
    const float* b_base = (const float*)d_in[6];
    const float* w_dir  = (const float*)d_in[7];
    const float* b_dir  = (const float*)d_in[8];
    const float* w_mag  = (const float*)d_in[9];
    const float* b_mag  = (const float*)d_in[10];

    prep_kernel<<<608, 256>>>(w_ih, w_hh, w_base);
    actor_kernel<<<128, 512>>>(x, b_ih, b_hh, b_base, w_dir, b_dir, w_mag, b_mag,
                               (float*)d_out);
}